// round 17
// baseline (speedup 1.0000x reference)
#include <cuda_runtime.h>

// NBVLoss: weighted BCE sum over predictions[16384,4096], target[16384,4096], t in {0,1}
//   out = sum_i  w_i * ( -max(log x_i, -100) ),  x_i = t? p : 1-p,  w = t? 1.6 : 0.4
//
// HBM-streaming reduction at the roofline:
//   - SINGLE WAVE: grid = 148 SMs x 8 blocks/SM = 1184 blocks (no wave-2 tail)
//   - float4 grid-stride, 4x manual unroll (8 front-batched LDG.128 -> MLP)
//   - __ldcs streaming loads (zero reuse; don't thrash L2)
//   - 32-bit indexing
//   - __log2f with ln2 folded into the weights:
//       w*max(ln(x),-100) = (w*ln2)*max(log2(x), -100/ln2)
//   - block reduce -> __device__ scratch; last block (atomic ticket) finishes
//     and writes d_out[0]. Deterministic, single launch.

#define NBV_BLOCKS  1184          // 148 SMs * 8 resident blocks = one full wave
#define NBV_THREADS 256

#define NBV_W1   (-1.10903548889591f)   /* -1.6 * ln2 */
#define NBV_W0   (-0.27725887222397f)   /* -0.4 * ln2 */
#define NBV_CLMP (-144.26950408889634f) /* -100 / ln2 */

__device__ float        g_nbv_partials[NBV_BLOCKS];
__device__ unsigned int g_nbv_ticket;   // zero-init; reset by last block each launch

__device__ __forceinline__ float nbv_term(float p, float t) {
    // t is exactly 0.0f or 1.0f
    float x = (t != 0.0f) ? p : (1.0f - p);
    float w = (t != 0.0f) ? NBV_W1 : NBV_W0;
    float l = fmaxf(__log2f(x), NBV_CLMP);   // __log2f(0) = -inf, clamped
    return w * l;
}

__device__ __forceinline__ float nbv_quad(float4 p, float4 t) {
    return nbv_term(p.x, t.x) + nbv_term(p.y, t.y)
         + nbv_term(p.z, t.z) + nbv_term(p.w, t.w);
}

__device__ __forceinline__ float block_reduce(float acc, float* s_warp, int nwarps) {
    #pragma unroll
    for (int off = 16; off > 0; off >>= 1)
        acc += __shfl_xor_sync(0xFFFFFFFFu, acc, off);
    const int lane = threadIdx.x & 31;
    const int wid  = threadIdx.x >> 5;
    if (lane == 0) s_warp[wid] = acc;
    __syncthreads();
    float v = 0.0f;
    if (wid == 0) {
        v = (lane < nwarps) ? s_warp[lane] : 0.0f;
        #pragma unroll
        for (int off = 16; off > 0; off >>= 1)
            v += __shfl_xor_sync(0xFFFFFFFFu, v, off);
    }
    return v;  // valid in warp 0
}

__global__ void __launch_bounds__(NBV_THREADS, 8)
nbv_kernel(const float4* __restrict__ pred4,
           const float4* __restrict__ targ4,
           unsigned int n4,
           float* __restrict__ out)
{
    const unsigned int stride = gridDim.x * blockDim.x;
    unsigned int i = blockIdx.x * blockDim.x + threadIdx.x;

    float acc = 0.0f;

    // main loop: 4 pairs in flight (8 x LDG.128 front-batched)
    for (; i + 3u * stride < n4; i += 4u * stride) {
        float4 p0 = __ldcs(pred4 + i);
        float4 p1 = __ldcs(pred4 + i + stride);
        float4 p2 = __ldcs(pred4 + i + 2u * stride);
        float4 p3 = __ldcs(pred4 + i + 3u * stride);
        float4 t0 = __ldcs(targ4 + i);
        float4 t1 = __ldcs(targ4 + i + stride);
        float4 t2 = __ldcs(targ4 + i + 2u * stride);
        float4 t3 = __ldcs(targ4 + i + 3u * stride);
        acc += nbv_quad(p0, t0);
        acc += nbv_quad(p1, t1);
        acc += nbv_quad(p2, t2);
        acc += nbv_quad(p3, t3);
    }
    // tail
    for (; i < n4; i += stride)
        acc += nbv_quad(__ldcs(pred4 + i), __ldcs(targ4 + i));

    __shared__ float s_warp[NBV_THREADS / 32];
    float bsum = block_reduce(acc, s_warp, NBV_THREADS / 32);

    __shared__ bool s_last;
    if (threadIdx.x == 0) {
        g_nbv_partials[blockIdx.x] = bsum;
        __threadfence();
        unsigned int tk = atomicAdd(&g_nbv_ticket, 1u);
        s_last = (tk == gridDim.x - 1u);
    }
    __syncthreads();

    if (s_last) {
        float a = 0.0f;
        for (int j = threadIdx.x; j < (int)gridDim.x; j += NBV_THREADS)
            a += g_nbv_partials[j];
        __shared__ float s_warp2[NBV_THREADS / 32];
        float total = block_reduce(a, s_warp2, NBV_THREADS / 32);
        if (threadIdx.x == 0) {
            out[0] = total;
            g_nbv_ticket = 0;   // reset for next graph replay
        }
    }
}

extern "C" void kernel_launch(void* const* d_in, const int* in_sizes, int n_in,
                              void* d_out, int out_size)
{
    const float* pred = (const float*)d_in[0];
    const float* targ = (const float*)d_in[1];
    float* out = (float*)d_out;

    const unsigned int n  = (unsigned int)in_sizes[0];  // 16384*4096, divisible by 4
    const unsigned int n4 = n >> 2;

    nbv_kernel<<<NBV_BLOCKS, NBV_THREADS>>>(
        (const float4*)pred, (const float4*)targ, n4, out);
}